// round 15
// baseline (speedup 1.0000x reference)
#include <cuda_runtime.h>

#define NPTS   8192
#define DM     128
#define DC     64
#define DF     256
#define GRIDS  96
#define NCELLS (96*96*96)
#define CAP    6
#define MK     16
#define SBLK   32
#define WFULL  0xffffffffu

typedef unsigned long long u64;

// ---------------- scratch (no allocations allowed) ----------------
__device__ float g_src [NPTS*DM];
__device__ float g_q   [NPTS*DM];
__device__ float g_k   [NPTS*DM];
__device__ float g_v   [NPTS*DM];
__device__ float g_ho  [NPTS*DM];
__device__ float g_fused[NPTS*DC];
__device__ float g_psum[SBLK][DC];
__device__ float g_psq [SBLK][DC];
__device__ int   g_nbr [NPTS*MK];
__device__ int   g_cnt [NCELLS];      // zero-initialized; attn tail restores zeros
__device__ int   g_cell[NCELLS*CAP];

// ---------------- packed fp32x2 helpers ----------------
__device__ __forceinline__ u64 pk2(float a, float b) {
    u64 r; asm("mov.b64 %0,{%1,%2};" : "=l"(r) : "f"(a), "f"(b)); return r;
}
__device__ __forceinline__ void upk2(u64 v, float& a, float& b) {
    asm("mov.b64 {%0,%1},%2;" : "=f"(a), "=f"(b) : "l"(v));
}
__device__ __forceinline__ void fma2(u64& d, u64 a, u64 b) {
    asm("fma.rn.f32x2 %0,%1,%2,%0;" : "+l"(d) : "l"(a), "l"(b));
}

// ---------------- cp.async helpers ----------------
__device__ __forceinline__ unsigned smem_u32(const void* p) {
    return (unsigned)__cvta_generic_to_shared(p);
}
__device__ __forceinline__ void cpa16(unsigned dst, const void* src) {
    asm volatile("cp.async.cg.shared.global [%0], [%1], 16;" :: "r"(dst), "l"(src));
}
#define CP_COMMIT() asm volatile("cp.async.commit_group;" ::: "memory")
#define CP_WAIT0()  asm volatile("cp.async.wait_group 0;" ::: "memory")

__device__ __forceinline__ float warpAllSum(float v) {
#pragma unroll
    for (int o = 16; o > 0; o >>= 1) v += __shfl_xor_sync(WFULL, v, o);
    return v;
}

// col-split smem layout: NR rows, 2 cols/lane (LDS.64 weights)
template<int NR>
__device__ __forceinline__ void sacc2(const float* A, int lda,
                                      const float* W, int ldw, int c0, int K,
                                      u64* a) {
#pragma unroll 2
    for (int e0 = 0; e0 < K; e0 += 4) {
        float4 av[NR];
#pragma unroll
        for (int r = 0; r < NR; r++)
            av[r] = *(const float4*)(A + r*lda + e0);
#pragma unroll
        for (int ee = 0; ee < 4; ee++) {
            u64 wv = *(const u64*)(W + (e0+ee)*ldw + c0);
#pragma unroll
            for (int r = 0; r < NR; r++) {
                float x = (ee==0)?av[r].x:(ee==1)?av[r].y:(ee==2)?av[r].z:av[r].w;
                fma2(a[r], pk2(x, x), wv);
            }
        }
    }
}

// col-split GLOBAL-weight accumulate: NR rows, 2 cols/lane (LDG.64), smem A
template<int NR>
__device__ __forceinline__ void gacc2(const float* A, int lda,
                                      const float* __restrict__ W, int ldw,
                                      int c0, int K, u64* a) {
#pragma unroll 2
    for (int e0 = 0; e0 < K; e0 += 4) {
        float4 av[NR];
#pragma unroll
        for (int r = 0; r < NR; r++)
            av[r] = *(const float4*)(A + r*lda + e0);
#pragma unroll
        for (int ee = 0; ee < 4; ee++) {
            u64 wv = __double_as_longlong(__ldg((const double*)(W + (e0+ee)*ldw + c0)));
#pragma unroll
            for (int r = 0; r < NR; r++) {
                float x = (ee==0)?av[r].x:(ee==1)?av[r].y:(ee==2)?av[r].z:av[r].w;
                fma2(a[r], pk2(x, x), wv);
            }
        }
    }
}

// col-split GLOBAL-weight, 16 rows/thread, float2 A loads (low reg pressure)
__device__ __forceinline__ void gacc2w(const float* A, int lda,
                                       const float* __restrict__ W, int ldw,
                                       int c0, int K, u64* a) {
#pragma unroll 2
    for (int e0 = 0; e0 < K; e0 += 2) {
        float2 av[16];
#pragma unroll
        for (int r = 0; r < 16; r++)
            av[r] = *(const float2*)(A + r*lda + e0);
#pragma unroll
        for (int ee = 0; ee < 2; ee++) {
            u64 wv = __double_as_longlong(__ldg((const double*)(W + (e0+ee)*ldw + c0)));
#pragma unroll
            for (int r = 0; r < 16; r++) {
                float x = (ee==0) ? av[r].x : av[r].y;
                fma2(a[r], pk2(x, x), wv);
            }
        }
    }
}

// R3-style global-weight accumulate: ROWS x 4 cols, fma2, __ldg double2
template<int ROWS, int K, int LDA>
__device__ __forceinline__ void gaccG(const float* A,
                                      const float* __restrict__ W, int ldw, int c0,
                                      u64* a01, u64* a23) {
#pragma unroll 2
    for (int e0 = 0; e0 < K; e0 += 4) {
        float4 av[ROWS];
#pragma unroll
        for (int r = 0; r < ROWS; r++)
            av[r] = *(const float4*)(A + r*LDA + e0);
#pragma unroll
        for (int ee = 0; ee < 4; ee++) {
            double2 wd = __ldg((const double2*)(W + (e0+ee)*ldw + c0));
            u64 w01 = __double_as_longlong(wd.x), w23 = __double_as_longlong(wd.y);
#pragma unroll
            for (int r = 0; r < ROWS; r++) {
                float x = (ee==0)?av[r].x:(ee==1)?av[r].y:(ee==2)?av[r].z:av[r].w;
                u64 a2 = pk2(x, x);
                fma2(a01[r], a2, w01); fma2(a23[r], a2, w23);
            }
        }
    }
}

// ---------------- grid build ----------------
__global__ void k_scatter(const int* __restrict__ coords, int N) {
    int i = blockIdx.x * blockDim.x + threadIdx.x;
    if (i >= N) return;
    int x = coords[3*i], y = coords[3*i+1], z = coords[3*i+2];
    int cid = (x * GRIDS + y) * GRIDS + z;
    int s = atomicAdd(&g_cnt[cid], 1);
    if (s < CAP) g_cell[cid*CAP + s] = i;
}

// exact jax.lax.top_k(-dist, 16): sort by (dist, index) ascending.
// MLP-batched: smem offset table + 8-wide independent cnt loads.
__global__ __launch_bounds__(128)
void k_nbr(const int* __restrict__ coords, int N) {
    __shared__ int4 offs[136];      // (dx,dy,dz,d), 129 valid + pad
    int t = threadIdx.x;
    if (t == 0) {
        int n = 0;
        for (int dx = -4; dx <= 4; dx++) {
            int rx = 4 - abs(dx);
            for (int dy = -rx; dy <= rx; dy++) {
                int rz = rx - abs(dy);
                for (int dz = -rz; dz <= rz; dz++)
                    offs[n++] = make_int4(dx, dy, dz, abs(dx)+abs(dy)+abs(dz));
            }
        }
        for (; n < 136; n++) offs[n] = make_int4(0, 0, 0, -1);  // pad invalid
    }
    __syncthreads();

    int i = blockIdx.x * 128 + t;
    if (i >= N) return;
    int x = coords[3*i], y = coords[3*i+1], z = coords[3*i+2];
    int best[MK];
#pragma unroll
    for (int m = 0; m < MK; m++) best[m] = 0x7fffffff;

    for (int b = 0; b < 136; b += 8) {
        int cids[8], cnts[8];
#pragma unroll
        for (int j = 0; j < 8; j++) {
            int4 o = offs[b + j];
            int nx = x + o.x, ny = y + o.y, nz = z + o.z;
            bool inb = (o.w >= 0) & (nx >= 0) & (nx < GRIDS) &
                       (ny >= 0) & (ny < GRIDS) & (nz >= 0) & (nz < GRIDS);
            cids[j] = inb ? (nx * GRIDS + ny) * GRIDS + nz : 0;
            cnts[j] = inb ? __ldg(&g_cnt[cids[j]]) : 0;   // 8 independent LDGs (MLP)
        }
#pragma unroll
        for (int j = 0; j < 8; j++) {
            int cnt = cnts[j] > CAP ? CAP : cnts[j];
            if (cnt > 0) {
                int d = offs[b + j].w;
                for (int s = 0; s < cnt; s++) {
                    int jj = __ldg(&g_cell[cids[j]*CAP + s]);
                    int key = (d << 13) | jj;
                    if (key < best[MK-1]) {
                        best[MK-1] = key;
#pragma unroll
                        for (int m = MK-1; m > 0; m--) {
                            if (best[m] < best[m-1]) {
                                int tmp = best[m-1]; best[m-1] = best[m]; best[m] = tmp;
                            }
                        }
                    }
                }
            }
        }
    }
#pragma unroll
    for (int m = 0; m < MK; m++)
        g_nbr[i*MK + m] = (best[m] == 0x7fffffff) ? -1 : (best[m] & 8191);
}

// ---- fused src(+PE) -> q/k/v : 32-row tiles, col-split warps, cp.async
// dynamic smem (floats): F[2048] H[2048] S[4096] Wb[16384]  = 96KB
__global__ __launch_bounds__(256, 2)
void k_srcproj(const float* __restrict__ feat, const int* __restrict__ coords,
               const float* __restrict__ pe_w1, const float* __restrict__ pe_b1,
               const float* __restrict__ pe_w2, const float* __restrict__ pe_b2,
               const float* __restrict__ in_w,  const float* __restrict__ in_b,
               const float* __restrict__ qw, const float* __restrict__ qb,
               const float* __restrict__ kw, const float* __restrict__ kb,
               const float* __restrict__ vw, const float* __restrict__ vb) {
    extern __shared__ float sm[];
    float* F  = sm;             // 32 x 64
    float* H  = sm + 2048;      // 32 x 64
    float* S  = sm + 4096;      // 32 x 128
    float* Wb = sm + 8192;      // 16384 floats

    int row0 = blockIdx.x * 32;
    int t = threadIdx.x;
    int lane = t & 31, w = t >> 5;
    int ch = w & 1, rg = w >> 1;
    int c0 = ch*64 + lane*2;    // 2 cols per lane
    int r0 = rg*8;              // 8 rows per thread

    // stage A weights via cp.async: in_w (2048 f4) | pe_w2 (2048 f4)
    {
        unsigned d = smem_u32(Wb);
#pragma unroll
        for (int k = 0; k < 16; k++) {
            int i = t + k*256;
            const char* srcp = (i < 2048) ? (const char*)in_w + i*16
                                          : (const char*)pe_w2 + (i-2048)*16;
            cpa16(d + i*16, srcp);
        }
        CP_COMMIT();
    }
    for (int i = t; i < 512; i += 256)
        ((float4*)F)[i] = __ldg(((const float4*)(feat + row0*DC)) + i);
    for (int i = t; i < 32*64; i += 256) {
        int r = i >> 6, hc = i & 63;
        int gi = row0 + r;
        float vx = (float)coords[3*gi]   * (1.0f/95.0f);
        float vy = (float)coords[3*gi+1] * (1.0f/95.0f);
        float vz = (float)coords[3*gi+2] * (1.0f/95.0f);
        float h = pe_b1[hc] + vx*pe_w1[hc] + vy*pe_w1[64+hc] + vz*pe_w1[128+hc];
        H[i] = fmaxf(h, 0.0f);
    }
    CP_WAIT0();
    __syncthreads();

    // ---- stage A: src = F@in_w + H@pe_w2 + biases -> S, g_src ----
    u64 a[8] = {0,0,0,0,0,0,0,0};
    sacc2<8>(F + r0*DC, DC, Wb, DM, c0, DC, a);     // stream F x in_w
    __syncthreads();   // in_w region now dead everywhere

    // issue stage-B chunk 0 into Wb[0..6144) while stream H computes
    {
        unsigned d = smem_u32(Wb);
#pragma unroll
        for (int k = 0; k < 6; k++) {
            int i = t + k*256;            // 1536 f4
            int sub = i >> 9, off = i & 511;
            const char* srcp = (sub == 0) ? (const char*)qw
                             : (sub == 1) ? (const char*)kw : (const char*)vw;
            cpa16(d + (sub*2048 + off*4)*4, srcp + off*16);
        }
        CP_COMMIT();
    }
    sacc2<8>(H + r0*64, 64, Wb + 8192, DM, c0, 64, a);   // stream H x pe_w2
    {
        float2 b1 = __ldg((const float2*)(in_b  + c0));
        float2 b2 = __ldg((const float2*)(pe_b2 + c0));
#pragma unroll
        for (int r = 0; r < 8; r++) {
            float v0,v1;
            upk2(a[r], v0, v1);
            float2 o = make_float2(v0+b1.x+b2.x, v1+b1.y+b2.y);
            *(float2*)(S + (r0+r)*DM + c0) = o;
            *(float2*)(g_src + (row0+r0+r)*DM + c0) = o;
        }
    }
    CP_WAIT0();
    __syncthreads();   // S complete + chunk 0 landed

    // ---- stage B: q/k/v fused, 8 ping-pong chunks of K=16 ----
    u64 qa[8]={0,0,0,0,0,0,0,0};
    u64 ka[8]={0,0,0,0,0,0,0,0};
    u64 va[8]={0,0,0,0,0,0,0,0};

    for (int c = 0; c < 8; c++) {
        float* buf = Wb + ((c & 1) ? 8192 : 0);
        if (c < 7) {
            float* nbuf = Wb + (((c+1) & 1) ? 8192 : 0);
            unsigned d = smem_u32(nbuf);
#pragma unroll
            for (int k = 0; k < 6; k++) {
                int i = t + k*256;
                int sub = i >> 9, off = i & 511;
                const char* srcp = (sub == 0) ? (const char*)qw
                                 : (sub == 1) ? (const char*)kw : (const char*)vw;
                cpa16(d + (sub*2048 + off*4)*4, srcp + ((c+1)*512 + off)*16);
            }
            CP_COMMIT();
        }
        const float* Wq = buf, *Wk = buf + 2048, *Wv = buf + 4096;
#pragma unroll 2
        for (int e0 = 0; e0 < 16; e0 += 4) {
            float4 av[8];
#pragma unroll
            for (int r = 0; r < 8; r++)
                av[r] = *(const float4*)(S + (r0+r)*DM + (c<<4) + e0);
#pragma unroll
            for (int ee = 0; ee < 4; ee++) {
                u64 wq = *(const u64*)(Wq + (e0+ee)*DM + c0);
                u64 wk = *(const u64*)(Wk + (e0+ee)*DM + c0);
                u64 wv = *(const u64*)(Wv + (e0+ee)*DM + c0);
#pragma unroll
                for (int r = 0; r < 8; r++) {
                    float x = (ee==0)?av[r].x:(ee==1)?av[r].y:(ee==2)?av[r].z:av[r].w;
                    u64 a2 = pk2(x, x);
                    fma2(qa[r], a2, wq);
                    fma2(ka[r], a2, wk);
                    fma2(va[r], a2, wv);
                }
            }
        }
        if (c < 7) CP_WAIT0();
        __syncthreads();
    }
    float2 bq = __ldg((const float2*)(qb + c0));
    float2 bk = __ldg((const float2*)(kb + c0));
    float2 bv = __ldg((const float2*)(vb + c0));
#pragma unroll
    for (int r = 0; r < 8; r++) {
        int grow = row0 + r0 + r;
        float v0,v1;
        upk2(qa[r], v0, v1);
        *(float2*)(g_q + grow*DM + c0) = make_float2(v0+bq.x, v1+bq.y);
        upk2(ka[r], v0, v1);
        *(float2*)(g_k + grow*DM + c0) = make_float2(v0+bk.x, v1+bk.y);
        upk2(va[r], v0, v1);
        *(float2*)(g_v + grow*DM + c0) = make_float2(v0+bv.x, v1+bv.y);
    }
}

// ---- attention: smem-free direct-gather, deferred V, fused g_cnt cleanup
__global__ __launch_bounds__(256)
void k_attn(const float* __restrict__ kb, const float* __restrict__ vb,
            const int* __restrict__ coords) {
    int n = blockIdx.x * 2 + (threadIdx.x >> 7);
    int t = threadIdx.x & 127;
    int h = t >> 5, lane = t & 31;
    const int* nb = g_nbr + n*MK;

    int j0 = __ldg(nb);
    float qv = (j0 >= 0) ? __ldg(g_q + j0*DM + t) : 0.f;

    int jr[4];
#pragma unroll
    for (int r = 0; r < 4; r++) jr[r] = __ldg(nb + (h<<2) + r);

    // K phase
    float sc[MK];
    {
        float kvv[MK];
#pragma unroll
        for (int m = 0; m < MK; m++) {
            int j = jr[m>>2];
            int col = ((m&3)<<5) + lane;
            kvv[m] = (j >= 0) ? __ldg(g_k + j*DM + col) : __ldg(kb + col);
        }
#pragma unroll
        for (int m = 0; m < MK; m++)
            sc[m] = warpAllSum(qv * kvv[m]) * 0.0883883476483184405f;  // 1/sqrt(128)
    }

    float mx = sc[0];
#pragma unroll
    for (int m = 1; m < MK; m++) mx = fmaxf(mx, sc[m]);
    float se = 0.f;
#pragma unroll
    for (int m = 0; m < MK; m++) { sc[m] = __expf(sc[m] - mx); se += sc[m]; }
    float inv = 1.f / se;

    // V phase (K regs dead)
    float o = 0.f;
    {
        float vvv[MK];
#pragma unroll
        for (int m = 0; m < MK; m++) {
            int j = jr[m>>2];
            int col = ((m&3)<<5) + lane;
            vvv[m] = (j >= 0) ? __ldg(g_v + j*DM + col) : __ldg(vb + col);
        }
#pragma unroll
        for (int m = 0; m < MK; m++)
            o += sc[m] * inv * vvv[m];
    }
    g_ho[n*DM + t] = o;

    // fused cleanup: zero this point's g_cnt cell (nbr is globally done)
    if (t == 0) {
        int cid = (__ldg(coords + 3*n) * GRIDS + __ldg(coords + 3*n + 1)) * GRIDS
                  + __ldg(coords + 3*n + 2);
        g_cnt[cid] = 0;
    }
}

// ------- mega kernel: col-split stages 1/2/3, old layout stage 4 --------
__global__ __launch_bounds__(256)
void k_mega(const float* __restrict__ ow, const float* __restrict__ ob,
            const float* __restrict__ n1g, const float* __restrict__ n1b,
            const float* __restrict__ w1, const float* __restrict__ b1,
            const float* __restrict__ w2, const float* __restrict__ b2,
            const float* __restrict__ n3g, const float* __restrict__ n3b,
            const float* __restrict__ feat,
            const float* __restrict__ fw, const float* __restrict__ fb) {
    __shared__ float T[32*DM];
    __shared__ float U[32*DF];
    __shared__ float F[32*DC];
    __shared__ float2 RED[64];     // [2 ch][32 rows] (sum, sumsq)
    int row0 = blockIdx.x * 32;
    int t = threadIdx.x;
    int lane = t & 31, w = t >> 5;
    int ch = w & 1, rg = w >> 1;
    int c0 = ch*64 + lane*2;       // col-split: 2 cols/lane
    int r0 = rg*8;                 // 8 rows/thread

    for (int i = t; i < 32*DM/4; i += 256)
        ((float4*)U)[i] = *(((const float4*)(g_ho + row0*DM)) + i);
    for (int i = t; i < 32*DC/4; i += 256)
        ((float4*)F)[i] = __ldg(((const float4*)(feat + row0*DC)) + i);
    __syncthreads();

    // ---- stage 1: out-proj (col-split) + residual(src) + LN1 -> T ----
    {
        u64 a[8]={0,0,0,0,0,0,0,0};
        gacc2<8>(U + r0*DM, DM, ow, DM, c0, DM, a);
        float2 b  = __ldg((const float2*)(ob  + c0));
        float2 g4 = __ldg((const float2*)(n1g + c0));
        float2 bb = __ldg((const float2*)(n1b + c0));
        float vv0[8], vv1[8];
#pragma unroll
        for (int r = 0; r < 8; r++) {
            float2 s = *(const float2*)(g_src + (row0+r0+r)*DM + c0);
            float v0,v1;
            upk2(a[r], v0, v1);
            v0 += b.x + s.x; v1 += b.y + s.y;
            vv0[r] = v0; vv1[r] = v1;
            float ps = warpAllSum(v0 + v1);
            float pq = warpAllSum(v0*v0 + v1*v1);
            if (lane == 0) RED[ch*32 + r0 + r] = make_float2(ps, pq);
        }
        __syncthreads();
#pragma unroll
        for (int r = 0; r < 8; r++) {
            float2 h0 = RED[r0 + r], h1 = RED[32 + r0 + r];
            float mean = (h0.x + h1.x) * (1.f/128.f);
            float var  = (h0.y + h1.y) * (1.f/128.f) - mean*mean;
            float rs = rsqrtf(var + 1e-5f);
            *(float2*)(T + (r0+r)*DM + c0) =
                make_float2((vv0[r]-mean)*rs*g4.x+bb.x, (vv1[r]-mean)*rs*g4.y+bb.y);
        }
    }
    __syncthreads();

    // ---- stage 2: FFN1 (128->256, relu), col-split 2 cols/lane -> U ----
    {
        int cq = w & 3, rg2 = w >> 2;      // 4 col-quads x 2 rowgroups
        int c2 = cq*64 + lane*2;
        int r2 = rg2*16;
        u64 a[16];
#pragma unroll
        for (int r = 0; r < 16; r++) a[r] = 0;
        gacc2w(T + r2*DM, DM, w1, DF, c2, DM, a);
        float2 b = __ldg((const float2*)(b1 + c2));
        __syncthreads();   // all stage-1 reads of U done before overwrite
#pragma unroll
        for (int r = 0; r < 16; r++) {
            float v0,v1;
            upk2(a[r], v0, v1);
            *(float2*)(U + (r2+r)*DF + c2) =
                make_float2(fmaxf(v0+b.x,0.f), fmaxf(v1+b.y,0.f));
        }
    }
    __syncthreads();

    // ---- stage 3: FFN2 (256->128, col-split) + residual(T) + LN3 -> T ----
    {
        u64 a[8]={0,0,0,0,0,0,0,0};
        gacc2<8>(U + r0*DF, DF, w2, DM, c0, DF, a);
        float2 b  = __ldg((const float2*)(b2  + c0));
        float2 g4 = __ldg((const float2*)(n3g + c0));
        float2 bb = __ldg((const float2*)(n3b + c0));
        float vv0[8], vv1[8];
#pragma unroll
        for (int r = 0; r < 8; r++) {
            float2 tp = *(const float2*)(T + (r0+r)*DM + c0);
            float v0,v1;
            upk2(a[r], v0, v1);
            v0 += b.x + tp.x; v1 += b.y + tp.y;
            vv0[r] = v0; vv1[r] = v1;
            float ps = warpAllSum(v0 + v1);
            float pq = warpAllSum(v0*v0 + v1*v1);
            if (lane == 0) RED[ch*32 + r0 + r] = make_float2(ps, pq);
        }
        __syncthreads();
#pragma unroll
        for (int r = 0; r < 8; r++) {
            float2 h0 = RED[r0 + r], h1 = RED[32 + r0 + r];
            float mean = (h0.x + h1.x) * (1.f/128.f);
            float var  = (h0.y + h1.y) * (1.f/128.f) - mean*mean;
            float rs = rsqrtf(var + 1e-5f);
            *(float2*)(T + (r0+r)*DM + c0) =
                make_float2((vv0[r]-mean)*rs*g4.x+bb.x, (vv1[r]-mean)*rs*g4.y+bb.y);
        }
    }
    __syncthreads();

    // ---- stage 4: fusion GEMM concat(F, T) @ fw + fb -> g_fused ----
    {
        int cg = t & 15, rg4 = t >> 4;
        int c4 = cg*4, r4 = rg4*2;
        u64 a01[2]={0,0}, a23[2]={0,0};
        gaccG<2, DC, DC>(F + r4*DC, fw, DC, c4, a01, a23);
        gaccG<2, DM, DM>(T + r4*DM, fw + DC*DC, DC, c4, a01, a23);
        float4 b = __ldg((const float4*)(fb + c4));
#pragma unroll
        for (int r = 0; r < 2; r++) {
            float v0,v1,v2,v3;
            upk2(a01[r], v0, v1); upk2(a23[r], v2, v3);
            *(float4*)(g_fused + (row0+r4+r)*DC + c4) =
                make_float4(v0+b.x, v1+b.y, v2+b.z, v3+b.w);
        }
    }
}

// ------ batchnorm stats: pass 1 (coalesced partials, deterministic) --------
__global__ __launch_bounds__(256)
void k_stats1() {
    __shared__ float ss[256][4];
    __shared__ float sq[256][4];
    int blk = blockIdx.x;
    int t = threadIdx.x;
    int c4 = t & 15, rq = t >> 4;
    float s0=0,s1=0,s2=0,s3=0, q0=0,q1=0,q2=0,q3=0;
    const int rows = NPTS / SBLK;
    for (int r = rq; r < rows; r += 16) {
        float4 v = *(const float4*)(g_fused + (blk*rows + r)*DC + c4*4);
        s0+=v.x; s1+=v.y; s2+=v.z; s3+=v.w;
        q0+=v.x*v.x; q1+=v.y*v.y; q2+=v.z*v.z; q3+=v.w*v.w;
    }
    ss[t][0]=s0; ss[t][1]=s1; ss[t][2]=s2; ss[t][3]=s3;
    sq[t][0]=q0; sq[t][1]=q1; sq[t][2]=q2; sq[t][3]=q3;
    __syncthreads();
    for (int st = 8; st > 0; st >>= 1) {
        if (rq < st) {
            int o = ((rq+st)<<4) | c4;
#pragma unroll
            for (int j = 0; j < 4; j++) { ss[t][j]+=ss[o][j]; sq[t][j]+=sq[o][j]; }
        }
        __syncthreads();
    }
    if (rq == 0) {
#pragma unroll
        for (int j = 0; j < 4; j++) {
            g_psum[blk][c4*4+j] = ss[t][j];
            g_psq [blk][c4*4+j] = sq[t][j];
        }
    }
}

// ---- output: final reduce of partials (per block) + normalize + relu ----
__global__ __launch_bounds__(256)
void k_out(const float* __restrict__ bng, const float* __restrict__ bnb,
           float* __restrict__ out, int total, int N) {
    __shared__ float s_mean[DC];
    __shared__ float s_scl [DC];
    int t = threadIdx.x;
    if (t < DC) {
        float s = 0.f, q = 0.f;
#pragma unroll 8
        for (int b = 0; b < SBLK; b++) { s += g_psum[b][t]; q += g_psq[b][t]; }
        float mean = s / (float)N;
        float var  = q / (float)N - mean*mean;
        s_mean[t] = mean;
        s_scl[t]  = rsqrtf(var + 1e-3f) * __ldg(bng + t);
    }
    __syncthreads();
    for (int i = blockIdx.x*blockDim.x + t; i < total; i += gridDim.x*blockDim.x) {
        int c = i & (DC-1);
        float v = (g_fused[i] - s_mean[c]) * s_scl[c] + __ldg(bnb + c);
        out[i] = fmaxf(v, 0.f);
    }
}

// ---------------- launch ----------------
extern "C" void kernel_launch(void* const* d_in, const int* in_sizes, int n_in,
                              void* d_out, int out_size) {
    const float* feat   = (const float*)d_in[0];
    const int*   coords = (const int*)  d_in[1];
    const float* pe_w1  = (const float*)d_in[2];
    const float* pe_b1  = (const float*)d_in[3];
    const float* pe_w2  = (const float*)d_in[4];
    const float* pe_b2  = (const float*)d_in[5];
    const float* in_w   = (const float*)d_in[6];
    const float* in_b   = (const float*)d_in[7];
    const float* q_w    = (const float*)d_in[8];
    const float* q_b    = (const float*)d_in[9];
    const float* k_w    = (const float*)d_in[10];
    const float* k_b    = (const float*)d_in[11];
    const float* v_w    = (const float*)d_in[12];
    const float* v_b    = (const float*)d_in[13];
    const float* o_w    = (const float*)d_in[14];
    const float* o_b    = (const float*)d_in[15];
    const float* n1_g   = (const float*)d_in[16];
    const float* n1_b   = (const float*)d_in[17];
    const float* l1_w   = (const float*)d_in[18];
    const float* l1_b   = (const float*)d_in[19];
    const float* l2_w   = (const float*)d_in[20];
    const float* l2_b   = (const float*)d_in[21];
    const float* n3_g   = (const float*)d_in[22];
    const float* n3_b   = (const float*)d_in[23];
    const float* fu_w   = (const float*)d_in[24];
    const float* fu_b   = (const float*)d_in[25];
    const float* bn_g   = (const float*)d_in[26];
    const float* bn_b   = (const float*)d_in[27];
    float* out = (float*)d_out;

    int N = in_sizes[0] / DC;   // 8192
    const int SRC_SMEM = 24576 * 4;   // 96KB
    cudaFuncSetAttribute(k_srcproj, cudaFuncAttributeMaxDynamicSharedMemorySize, SRC_SMEM);

    k_scatter<<<(N+255)/256, 256>>>(coords, N);
    k_nbr    <<<(N+127)/128, 128>>>(coords, N);
    k_srcproj<<<N/32, 256, SRC_SMEM>>>(feat, coords, pe_w1, pe_b1, pe_w2, pe_b2, in_w, in_b,
                                       q_w, q_b, k_w, k_b, v_w, v_b);
    k_attn   <<<N/2, 256>>>(k_b, v_b, coords);
    k_mega   <<<N/32, 256>>>(o_w, o_b, n1_g, n1_b, l1_w, l1_b, l2_w, l2_b,
                             n3_g, n3_b, feat, fu_w, fu_b);
    k_stats1 <<<SBLK, 256>>>();
    k_out    <<<256, 256>>>(bn_g, bn_b, out, N*DC, N);
}

// round 16
// speedup vs baseline: 1.0656x; 1.0656x over previous
#include <cuda_runtime.h>

#define NPTS   8192
#define DM     128
#define DC     64
#define DF     256
#define GRIDS  96
#define NCELLS (96*96*96)
#define CAP    6
#define MK     16
#define SBLK   32
#define WFULL  0xffffffffu

typedef unsigned long long u64;

// ---------------- scratch (no allocations allowed) ----------------
__device__ float g_src [NPTS*DM];
__device__ float g_q   [NPTS*DM];
__device__ float g_k   [NPTS*DM];
__device__ float g_v   [NPTS*DM];
__device__ float g_ho  [NPTS*DM];
__device__ float g_fused[NPTS*DC];
__device__ float g_psum[SBLK][DC];
__device__ float g_psq [SBLK][DC];
__device__ int   g_nbr [NPTS*MK];
__device__ int   g_cnt [NCELLS];      // zero-initialized; k_cleanup restores zeros
__device__ int   g_cell[NCELLS*CAP];

// ---------------- packed fp32x2 helpers ----------------
__device__ __forceinline__ u64 pk2(float a, float b) {
    u64 r; asm("mov.b64 %0,{%1,%2};" : "=l"(r) : "f"(a), "f"(b)); return r;
}
__device__ __forceinline__ void upk2(u64 v, float& a, float& b) {
    asm("mov.b64 {%0,%1},%2;" : "=f"(a), "=f"(b) : "l"(v));
}
__device__ __forceinline__ void fma2(u64& d, u64 a, u64 b) {
    asm("fma.rn.f32x2 %0,%1,%2,%0;" : "+l"(d) : "l"(a), "l"(b));
}

// ---------------- cp.async helpers ----------------
__device__ __forceinline__ unsigned smem_u32(const void* p) {
    return (unsigned)__cvta_generic_to_shared(p);
}
__device__ __forceinline__ void cpa16(unsigned dst, const void* src) {
    asm volatile("cp.async.cg.shared.global [%0], [%1], 16;" :: "r"(dst), "l"(src));
}
#define CP_COMMIT() asm volatile("cp.async.commit_group;" ::: "memory")
#define CP_WAIT0()  asm volatile("cp.async.wait_group 0;" ::: "memory")

__device__ __forceinline__ float warpAllSum(float v) {
#pragma unroll
    for (int o = 16; o > 0; o >>= 1) v += __shfl_xor_sync(WFULL, v, o);
    return v;
}

// col-split smem layout: NR rows, 2 cols/lane (LDS.64 weights)
template<int NR>
__device__ __forceinline__ void sacc2(const float* A, int lda,
                                      const float* W, int ldw, int c0, int K,
                                      u64* a) {
#pragma unroll 2
    for (int e0 = 0; e0 < K; e0 += 4) {
        float4 av[NR];
#pragma unroll
        for (int r = 0; r < NR; r++)
            av[r] = *(const float4*)(A + r*lda + e0);
#pragma unroll
        for (int ee = 0; ee < 4; ee++) {
            u64 wv = *(const u64*)(W + (e0+ee)*ldw + c0);
#pragma unroll
            for (int r = 0; r < NR; r++) {
                float x = (ee==0)?av[r].x:(ee==1)?av[r].y:(ee==2)?av[r].z:av[r].w;
                fma2(a[r], pk2(x, x), wv);
            }
        }
    }
}

// col-split GLOBAL-weight accumulate: NR rows, 2 cols/lane (LDG.64), smem A
template<int NR>
__device__ __forceinline__ void gacc2(const float* A, int lda,
                                      const float* __restrict__ W, int ldw,
                                      int c0, int K, u64* a) {
#pragma unroll 2
    for (int e0 = 0; e0 < K; e0 += 4) {
        float4 av[NR];
#pragma unroll
        for (int r = 0; r < NR; r++)
            av[r] = *(const float4*)(A + r*lda + e0);
#pragma unroll
        for (int ee = 0; ee < 4; ee++) {
            u64 wv = __double_as_longlong(__ldg((const double*)(W + (e0+ee)*ldw + c0)));
#pragma unroll
            for (int r = 0; r < NR; r++) {
                float x = (ee==0)?av[r].x:(ee==1)?av[r].y:(ee==2)?av[r].z:av[r].w;
                fma2(a[r], pk2(x, x), wv);
            }
        }
    }
}

// R3-style global-weight accumulate: ROWS x 4 cols, fma2, __ldg double2
template<int ROWS, int K, int LDA>
__device__ __forceinline__ void gaccG(const float* A,
                                      const float* __restrict__ W, int ldw, int c0,
                                      u64* a01, u64* a23) {
#pragma unroll 2
    for (int e0 = 0; e0 < K; e0 += 4) {
        float4 av[ROWS];
#pragma unroll
        for (int r = 0; r < ROWS; r++)
            av[r] = *(const float4*)(A + r*LDA + e0);
#pragma unroll
        for (int ee = 0; ee < 4; ee++) {
            double2 wd = __ldg((const double2*)(W + (e0+ee)*ldw + c0));
            u64 w01 = __double_as_longlong(wd.x), w23 = __double_as_longlong(wd.y);
#pragma unroll
            for (int r = 0; r < ROWS; r++) {
                float x = (ee==0)?av[r].x:(ee==1)?av[r].y:(ee==2)?av[r].z:av[r].w;
                u64 a2 = pk2(x, x);
                fma2(a01[r], a2, w01); fma2(a23[r], a2, w23);
            }
        }
    }
}

// ---------------- grid build (no clear: g_cnt kept zero via k_cleanup) -----
__global__ void k_scatter(const int* __restrict__ coords, int N) {
    int i = blockIdx.x * blockDim.x + threadIdx.x;
    if (i >= N) return;
    int x = coords[3*i], y = coords[3*i+1], z = coords[3*i+2];
    int cid = (x * GRIDS + y) * GRIDS + z;
    int s = atomicAdd(&g_cnt[cid], 1);
    if (s < CAP) g_cell[cid*CAP + s] = i;
}

// exact jax.lax.top_k(-dist, 16): sort by (dist, index) ascending.
// MLP-batched: smem offset table + 8-wide independent cnt loads.
__global__ __launch_bounds__(128)
void k_nbr(const int* __restrict__ coords, int N) {
    __shared__ int4 offs[136];      // (dx,dy,dz,d), 129 valid + pad
    int t = threadIdx.x;
    if (t == 0) {
        int n = 0;
        for (int dx = -4; dx <= 4; dx++) {
            int rx = 4 - abs(dx);
            for (int dy = -rx; dy <= rx; dy++) {
                int rz = rx - abs(dy);
                for (int dz = -rz; dz <= rz; dz++)
                    offs[n++] = make_int4(dx, dy, dz, abs(dx)+abs(dy)+abs(dz));
            }
        }
        for (; n < 136; n++) offs[n] = make_int4(0, 0, 0, -1);  // pad invalid
    }
    __syncthreads();

    int i = blockIdx.x * 128 + t;
    if (i >= N) return;
    int x = coords[3*i], y = coords[3*i+1], z = coords[3*i+2];
    int best[MK];
#pragma unroll
    for (int m = 0; m < MK; m++) best[m] = 0x7fffffff;

    for (int b = 0; b < 136; b += 8) {
        int cids[8], cnts[8];
#pragma unroll
        for (int j = 0; j < 8; j++) {
            int4 o = offs[b + j];
            int nx = x + o.x, ny = y + o.y, nz = z + o.z;
            bool inb = (o.w >= 0) & (nx >= 0) & (nx < GRIDS) &
                       (ny >= 0) & (ny < GRIDS) & (nz >= 0) & (nz < GRIDS);
            cids[j] = inb ? (nx * GRIDS + ny) * GRIDS + nz : 0;
            cnts[j] = inb ? __ldg(&g_cnt[cids[j]]) : 0;   // 8 independent LDGs (MLP)
        }
#pragma unroll
        for (int j = 0; j < 8; j++) {
            int cnt = cnts[j] > CAP ? CAP : cnts[j];
            if (cnt > 0) {
                int d = offs[b + j].w;
                for (int s = 0; s < cnt; s++) {
                    int jj = __ldg(&g_cell[cids[j]*CAP + s]);
                    int key = (d << 13) | jj;
                    if (key < best[MK-1]) {
                        best[MK-1] = key;
#pragma unroll
                        for (int m = MK-1; m > 0; m--) {
                            if (best[m] < best[m-1]) {
                                int tmp = best[m-1]; best[m-1] = best[m]; best[m] = tmp;
                            }
                        }
                    }
                }
            }
        }
    }
#pragma unroll
    for (int m = 0; m < MK; m++)
        g_nbr[i*MK + m] = (best[m] == 0x7fffffff) ? -1 : (best[m] & 8191);
}

// zero only the touched cells (idempotent; keeps g_cnt all-zero for next replay)
__global__ void k_cleanup(const int* __restrict__ coords, int N) {
    int i = blockIdx.x * blockDim.x + threadIdx.x;
    if (i >= N) return;
    int cid = (coords[3*i] * GRIDS + coords[3*i+1]) * GRIDS + coords[3*i+2];
    g_cnt[cid] = 0;
}

// ---- fused src(+PE) -> q/k/v : 32-row tiles, col-split warps, cp.async
// dynamic smem (floats): F[2048] H[2048] S[4096] Wb[16384]  = 96KB
__global__ __launch_bounds__(256, 2)
void k_srcproj(const float* __restrict__ feat, const int* __restrict__ coords,
               const float* __restrict__ pe_w1, const float* __restrict__ pe_b1,
               const float* __restrict__ pe_w2, const float* __restrict__ pe_b2,
               const float* __restrict__ in_w,  const float* __restrict__ in_b,
               const float* __restrict__ qw, const float* __restrict__ qb,
               const float* __restrict__ kw, const float* __restrict__ kb,
               const float* __restrict__ vw, const float* __restrict__ vb) {
    extern __shared__ float sm[];
    float* F  = sm;             // 32 x 64
    float* H  = sm + 2048;      // 32 x 64
    float* S  = sm + 4096;      // 32 x 128
    float* Wb = sm + 8192;      // 16384 floats

    int row0 = blockIdx.x * 32;
    int t = threadIdx.x;
    int lane = t & 31, w = t >> 5;
    int ch = w & 1, rg = w >> 1;
    int c0 = ch*64 + lane*2;    // 2 cols per lane
    int r0 = rg*8;              // 8 rows per thread

    // stage A weights via cp.async: in_w (2048 f4) | pe_w2 (2048 f4)
    {
        unsigned d = smem_u32(Wb);
#pragma unroll
        for (int k = 0; k < 16; k++) {
            int i = t + k*256;
            const char* srcp = (i < 2048) ? (const char*)in_w + i*16
                                          : (const char*)pe_w2 + (i-2048)*16;
            cpa16(d + i*16, srcp);
        }
        CP_COMMIT();
    }
    for (int i = t; i < 512; i += 256)
        ((float4*)F)[i] = __ldg(((const float4*)(feat + row0*DC)) + i);
    for (int i = t; i < 32*64; i += 256) {
        int r = i >> 6, hc = i & 63;
        int gi = row0 + r;
        float vx = (float)coords[3*gi]   * (1.0f/95.0f);
        float vy = (float)coords[3*gi+1] * (1.0f/95.0f);
        float vz = (float)coords[3*gi+2] * (1.0f/95.0f);
        float h = pe_b1[hc] + vx*pe_w1[hc] + vy*pe_w1[64+hc] + vz*pe_w1[128+hc];
        H[i] = fmaxf(h, 0.0f);
    }
    CP_WAIT0();
    __syncthreads();

    // ---- stage A: src = F@in_w + H@pe_w2 + biases -> S, g_src ----
    u64 a[8] = {0,0,0,0,0,0,0,0};
    sacc2<8>(F + r0*DC, DC, Wb, DM, c0, DC, a);     // stream F x in_w
    __syncthreads();   // in_w region now dead everywhere

    // issue stage-B chunk 0 into Wb[0..6144) while stream H computes
    {
        unsigned d = smem_u32(Wb);
#pragma unroll
        for (int k = 0; k < 6; k++) {
            int i = t + k*256;            // 1536 f4
            int sub = i >> 9, off = i & 511;
            const char* srcp = (sub == 0) ? (const char*)qw
                             : (sub == 1) ? (const char*)kw : (const char*)vw;
            cpa16(d + (sub*2048 + off*4)*4, srcp + off*16);
        }
        CP_COMMIT();
    }
    sacc2<8>(H + r0*64, 64, Wb + 8192, DM, c0, 64, a);   // stream H x pe_w2
    {
        float2 b1 = __ldg((const float2*)(in_b  + c0));
        float2 b2 = __ldg((const float2*)(pe_b2 + c0));
#pragma unroll
        for (int r = 0; r < 8; r++) {
            float v0,v1;
            upk2(a[r], v0, v1);
            float2 o = make_float2(v0+b1.x+b2.x, v1+b1.y+b2.y);
            *(float2*)(S + (r0+r)*DM + c0) = o;
            *(float2*)(g_src + (row0+r0+r)*DM + c0) = o;
        }
    }
    CP_WAIT0();
    __syncthreads();   // S complete + chunk 0 landed

    // ---- stage B: q/k/v fused, 8 ping-pong chunks of K=16 ----
    u64 qa[8]={0,0,0,0,0,0,0,0};
    u64 ka[8]={0,0,0,0,0,0,0,0};
    u64 va[8]={0,0,0,0,0,0,0,0};

    for (int c = 0; c < 8; c++) {
        float* buf = Wb + ((c & 1) ? 8192 : 0);
        if (c < 7) {
            float* nbuf = Wb + (((c+1) & 1) ? 8192 : 0);
            unsigned d = smem_u32(nbuf);
#pragma unroll
            for (int k = 0; k < 6; k++) {
                int i = t + k*256;
                int sub = i >> 9, off = i & 511;
                const char* srcp = (sub == 0) ? (const char*)qw
                                 : (sub == 1) ? (const char*)kw : (const char*)vw;
                cpa16(d + (sub*2048 + off*4)*4, srcp + ((c+1)*512 + off)*16);
            }
            CP_COMMIT();
        }
        const float* Wq = buf, *Wk = buf + 2048, *Wv = buf + 4096;
#pragma unroll 2
        for (int e0 = 0; e0 < 16; e0 += 4) {
            float4 av[8];
#pragma unroll
            for (int r = 0; r < 8; r++)
                av[r] = *(const float4*)(S + (r0+r)*DM + (c<<4) + e0);
#pragma unroll
            for (int ee = 0; ee < 4; ee++) {
                u64 wq = *(const u64*)(Wq + (e0+ee)*DM + c0);
                u64 wk = *(const u64*)(Wk + (e0+ee)*DM + c0);
                u64 wv = *(const u64*)(Wv + (e0+ee)*DM + c0);
#pragma unroll
                for (int r = 0; r < 8; r++) {
                    float x = (ee==0)?av[r].x:(ee==1)?av[r].y:(ee==2)?av[r].z:av[r].w;
                    u64 a2 = pk2(x, x);
                    fma2(qa[r], a2, wq);
                    fma2(ka[r], a2, wk);
                    fma2(va[r], a2, wv);
                }
            }
        }
        if (c < 7) CP_WAIT0();
        __syncthreads();
    }
    float2 bq = __ldg((const float2*)(qb + c0));
    float2 bk = __ldg((const float2*)(kb + c0));
    float2 bv = __ldg((const float2*)(vb + c0));
#pragma unroll
    for (int r = 0; r < 8; r++) {
        int grow = row0 + r0 + r;
        float v0,v1;
        upk2(qa[r], v0, v1);
        *(float2*)(g_q + grow*DM + c0) = make_float2(v0+bq.x, v1+bq.y);
        upk2(ka[r], v0, v1);
        *(float2*)(g_k + grow*DM + c0) = make_float2(v0+bk.x, v1+bk.y);
        upk2(va[r], v0, v1);
        *(float2*)(g_v + grow*DM + c0) = make_float2(v0+bv.x, v1+bv.y);
    }
}

// ---- attention: smem-free direct-gather, 2 points / 256-thread block ----
__global__ __launch_bounds__(256)
void k_attn(const float* __restrict__ kb, const float* __restrict__ vb) {
    int n = blockIdx.x * 2 + (threadIdx.x >> 7);
    int t = threadIdx.x & 127;
    int h = t >> 5, lane = t & 31;
    const int* nb = g_nbr + n*MK;

    int j0 = __ldg(nb);
    float qv = (j0 >= 0) ? __ldg(g_q + j0*DM + t) : 0.f;

    int jr[4];
#pragma unroll
    for (int r = 0; r < 4; r++) jr[r] = __ldg(nb + (h<<2) + r);

    float kvv[MK], vvv[MK];
#pragma unroll
    for (int m = 0; m < MK; m++) {
        int j = jr[m>>2];
        int col = ((m&3)<<5) + lane;
        kvv[m] = (j >= 0) ? __ldg(g_k + j*DM + col) : __ldg(kb + col);
        vvv[m] = (j >= 0) ? __ldg(g_v + j*DM + col) : __ldg(vb + col);
    }

    float sc[MK];
#pragma unroll
    for (int m = 0; m < MK; m++)
        sc[m] = warpAllSum(qv * kvv[m]) * 0.0883883476483184405f;  // 1/sqrt(128)

    float mx = sc[0];
#pragma unroll
    for (int m = 1; m < MK; m++) mx = fmaxf(mx, sc[m]);
    float se = 0.f;
#pragma unroll
    for (int m = 0; m < MK; m++) { sc[m] = __expf(sc[m] - mx); se += sc[m]; }
    float inv = 1.f / se;
    float o = 0.f;
#pragma unroll
    for (int m = 0; m < MK; m++)
        o += sc[m] * inv * vvv[m];
    g_ho[n*DM + t] = o;
}

// ------- mega kernel: col-split stages 1/3, old layout stages 2/4 --------
__global__ __launch_bounds__(256)
void k_mega(const float* __restrict__ ow, const float* __restrict__ ob,
            const float* __restrict__ n1g, const float* __restrict__ n1b,
            const float* __restrict__ w1, const float* __restrict__ b1,
            const float* __restrict__ w2, const float* __restrict__ b2,
            const float* __restrict__ n3g, const float* __restrict__ n3b,
            const float* __restrict__ feat,
            const float* __restrict__ fw, const float* __restrict__ fb) {
    __shared__ float T[32*DM];
    __shared__ float U[32*DF];
    __shared__ float F[32*DC];
    __shared__ float2 RED[64];     // [2 ch][32 rows] (sum, sumsq)
    int row0 = blockIdx.x * 32;
    int t = threadIdx.x;
    int lane = t & 31, w = t >> 5;
    int ch = w & 1, rg = w >> 1;
    int c0 = ch*64 + lane*2;       // col-split: 2 cols/lane
    int r0 = rg*8;                 // 8 rows/thread

    for (int i = t; i < 32*DM/4; i += 256)
        ((float4*)U)[i] = *(((const float4*)(g_ho + row0*DM)) + i);
    for (int i = t; i < 32*DC/4; i += 256)
        ((float4*)F)[i] = __ldg(((const float4*)(feat + row0*DC)) + i);
    __syncthreads();

    // ---- stage 1: out-proj (col-split) + residual(src) + LN1 -> T ----
    {
        u64 a[8]={0,0,0,0,0,0,0,0};
        gacc2<8>(U + r0*DM, DM, ow, DM, c0, DM, a);
        float2 b  = __ldg((const float2*)(ob  + c0));
        float2 g4 = __ldg((const float2*)(n1g + c0));
        float2 bb = __ldg((const float2*)(n1b + c0));
        float vv0[8], vv1[8];
#pragma unroll
        for (int r = 0; r < 8; r++) {
            float2 s = *(const float2*)(g_src + (row0+r0+r)*DM + c0);
            float v0,v1;
            upk2(a[r], v0, v1);
            v0 += b.x + s.x; v1 += b.y + s.y;
            vv0[r] = v0; vv1[r] = v1;
            float ps = warpAllSum(v0 + v1);
            float pq = warpAllSum(v0*v0 + v1*v1);
            if (lane == 0) RED[ch*32 + r0 + r] = make_float2(ps, pq);
        }
        __syncthreads();
#pragma unroll
        for (int r = 0; r < 8; r++) {
            float2 h0 = RED[r0 + r], h1 = RED[32 + r0 + r];
            float mean = (h0.x + h1.x) * (1.f/128.f);
            float var  = (h0.y + h1.y) * (1.f/128.f) - mean*mean;
            float rs = rsqrtf(var + 1e-5f);
            *(float2*)(T + (r0+r)*DM + c0) =
                make_float2((vv0[r]-mean)*rs*g4.x+bb.x, (vv1[r]-mean)*rs*g4.y+bb.y);
        }
    }
    __syncthreads();

    // ---- stage 2: FFN1 (128->256, relu) -> U ----
    {
        int cg = t & 63, rg2 = t >> 6;
        int c2 = cg*4, r2 = rg2*8;
        u64 a01[8]={0,0,0,0,0,0,0,0}, a23[8]={0,0,0,0,0,0,0,0};
        gaccG<8, DM, DM>(T + r2*DM, w1, DF, c2, a01, a23);
        float4 b = __ldg((const float4*)(b1 + c2));
        __syncthreads();   // all stage-1 reads of U done before overwrite
#pragma unroll
        for (int r = 0; r < 8; r++) {
            float v0,v1,v2,v3;
            upk2(a01[r], v0, v1); upk2(a23[r], v2, v3);
            float* up = U + (r2+r)*DF + c2;
            up[0]=fmaxf(v0+b.x,0.f); up[1]=fmaxf(v1+b.y,0.f);
            up[2]=fmaxf(v2+b.z,0.f); up[3]=fmaxf(v3+b.w,0.f);
        }
    }
    __syncthreads();

    // ---- stage 3: FFN2 (256->128, col-split) + residual(T) + LN3 -> T ----
    {
        u64 a[8]={0,0,0,0,0,0,0,0};
        gacc2<8>(U + r0*DF, DF, w2, DM, c0, DF, a);
        float2 b  = __ldg((const float2*)(b2  + c0));
        float2 g4 = __ldg((const float2*)(n3g + c0));
        float2 bb = __ldg((const float2*)(n3b + c0));
        float vv0[8], vv1[8];
#pragma unroll
        for (int r = 0; r < 8; r++) {
            float2 tp = *(const float2*)(T + (r0+r)*DM + c0);
            float v0,v1;
            upk2(a[r], v0, v1);
            v0 += b.x + tp.x; v1 += b.y + tp.y;
            vv0[r] = v0; vv1[r] = v1;
            float ps = warpAllSum(v0 + v1);
            float pq = warpAllSum(v0*v0 + v1*v1);
            if (lane == 0) RED[ch*32 + r0 + r] = make_float2(ps, pq);
        }
        __syncthreads();
#pragma unroll
        for (int r = 0; r < 8; r++) {
            float2 h0 = RED[r0 + r], h1 = RED[32 + r0 + r];
            float mean = (h0.x + h1.x) * (1.f/128.f);
            float var  = (h0.y + h1.y) * (1.f/128.f) - mean*mean;
            float rs = rsqrtf(var + 1e-5f);
            *(float2*)(T + (r0+r)*DM + c0) =
                make_float2((vv0[r]-mean)*rs*g4.x+bb.x, (vv1[r]-mean)*rs*g4.y+bb.y);
        }
    }
    __syncthreads();

    // ---- stage 4: fusion GEMM concat(F, T) @ fw + fb -> g_fused ----
    {
        int cg = t & 15, rg4 = t >> 4;
        int c4 = cg*4, r4 = rg4*2;
        u64 a01[2]={0,0}, a23[2]={0,0};
        gaccG<2, DC, DC>(F + r4*DC, fw, DC, c4, a01, a23);
        gaccG<2, DM, DM>(T + r4*DM, fw + DC*DC, DC, c4, a01, a23);
        float4 b = __ldg((const float4*)(fb + c4));
#pragma unroll
        for (int r = 0; r < 2; r++) {
            float v0,v1,v2,v3;
            upk2(a01[r], v0, v1); upk2(a23[r], v2, v3);
            *(float4*)(g_fused + (row0+r4+r)*DC + c4) =
                make_float4(v0+b.x, v1+b.y, v2+b.z, v3+b.w);
        }
    }
}

// ------ batchnorm stats: pass 1 (coalesced partials, deterministic) --------
__global__ __launch_bounds__(256)
void k_stats1() {
    __shared__ float ss[256][4];
    __shared__ float sq[256][4];
    int blk = blockIdx.x;
    int t = threadIdx.x;
    int c4 = t & 15, rq = t >> 4;
    float s0=0,s1=0,s2=0,s3=0, q0=0,q1=0,q2=0,q3=0;
    const int rows = NPTS / SBLK;
    for (int r = rq; r < rows; r += 16) {
        float4 v = *(const float4*)(g_fused + (blk*rows + r)*DC + c4*4);
        s0+=v.x; s1+=v.y; s2+=v.z; s3+=v.w;
        q0+=v.x*v.x; q1+=v.y*v.y; q2+=v.z*v.z; q3+=v.w*v.w;
    }
    ss[t][0]=s0; ss[t][1]=s1; ss[t][2]=s2; ss[t][3]=s3;
    sq[t][0]=q0; sq[t][1]=q1; sq[t][2]=q2; sq[t][3]=q3;
    __syncthreads();
    for (int st = 8; st > 0; st >>= 1) {
        if (rq < st) {
            int o = ((rq+st)<<4) | c4;
#pragma unroll
            for (int j = 0; j < 4; j++) { ss[t][j]+=ss[o][j]; sq[t][j]+=sq[o][j]; }
        }
        __syncthreads();
    }
    if (rq == 0) {
#pragma unroll
        for (int j = 0; j < 4; j++) {
            g_psum[blk][c4*4+j] = ss[t][j];
            g_psq [blk][c4*4+j] = sq[t][j];
        }
    }
}

// ---- output: final reduce of partials (per block) + normalize + relu ----
__global__ __launch_bounds__(256)
void k_out(const float* __restrict__ bng, const float* __restrict__ bnb,
           float* __restrict__ out, int total, int N) {
    __shared__ float s_mean[DC];
    __shared__ float s_scl [DC];
    int t = threadIdx.x;
    if (t < DC) {
        float s = 0.f, q = 0.f;
#pragma unroll 8
        for (int b = 0; b < SBLK; b++) { s += g_psum[b][t]; q += g_psq[b][t]; }
        float mean = s / (float)N;
        float var  = q / (float)N - mean*mean;
        s_mean[t] = mean;
        s_scl[t]  = rsqrtf(var + 1e-3f) * __ldg(bng + t);
    }
    __syncthreads();
    for (int i = blockIdx.x*blockDim.x + t; i < total; i += gridDim.x*blockDim.x) {
        int c = i & (DC-1);
        float v = (g_fused[i] - s_mean[c]) * s_scl[c] + __ldg(bnb + c);
        out[i] = fmaxf(v, 0.f);
    }
}

// ---------------- launch ----------------
extern "C" void kernel_launch(void* const* d_in, const int* in_sizes, int n_in,
                              void* d_out, int out_size) {
    const float* feat   = (const float*)d_in[0];
    const int*   coords = (const int*)  d_in[1];
    const float* pe_w1  = (const float*)d_in[2];
    const float* pe_b1  = (const float*)d_in[3];
    const float* pe_w2  = (const float*)d_in[4];
    const float* pe_b2  = (const float*)d_in[5];
    const float* in_w   = (const float*)d_in[6];
    const float* in_b   = (const float*)d_in[7];
    const float* q_w    = (const float*)d_in[8];
    const float* q_b    = (const float*)d_in[9];
    const float* k_w    = (const float*)d_in[10];
    const float* k_b    = (const float*)d_in[11];
    const float* v_w    = (const float*)d_in[12];
    const float* v_b    = (const float*)d_in[13];
    const float* o_w    = (const float*)d_in[14];
    const float* o_b    = (const float*)d_in[15];
    const float* n1_g   = (const float*)d_in[16];
    const float* n1_b   = (const float*)d_in[17];
    const float* l1_w   = (const float*)d_in[18];
    const float* l1_b   = (const float*)d_in[19];
    const float* l2_w   = (const float*)d_in[20];
    const float* l2_b   = (const float*)d_in[21];
    const float* n3_g   = (const float*)d_in[22];
    const float* n3_b   = (const float*)d_in[23];
    const float* fu_w   = (const float*)d_in[24];
    const float* fu_b   = (const float*)d_in[25];
    const float* bn_g   = (const float*)d_in[26];
    const float* bn_b   = (const float*)d_in[27];
    float* out = (float*)d_out;

    int N = in_sizes[0] / DC;   // 8192
    const int SRC_SMEM = 24576 * 4;   // 96KB
    cudaFuncSetAttribute(k_srcproj, cudaFuncAttributeMaxDynamicSharedMemorySize, SRC_SMEM);

    k_scatter<<<(N+255)/256, 256>>>(coords, N);
    k_nbr    <<<(N+127)/128, 128>>>(coords, N);
    k_srcproj<<<N/32, 256, SRC_SMEM>>>(feat, coords, pe_w1, pe_b1, pe_w2, pe_b2, in_w, in_b,
                                       q_w, q_b, k_w, k_b, v_w, v_b);
    k_attn   <<<N/2, 256>>>(k_b, v_b);
    k_mega   <<<N/32, 256>>>(o_w, o_b, n1_g, n1_b, l1_w, l1_b, l2_w, l2_b,
                             n3_g, n3_b, feat, fu_w, fu_b);
    k_stats1 <<<SBLK, 256>>>();
    k_out    <<<256, 256>>>(bn_g, bn_b, out, N*DC, N);
    k_cleanup<<<(N+255)/256, 256>>>(coords, N);
}